// round 1
// baseline (speedup 1.0000x reference)
#include <cuda_runtime.h>
#include <math.h>

// Problem constants
#define BB 2
#define SS 2048
#define DD 1024
#define HH 16
#define HDD 64
#define VV 50257
#define TT (BB*SS)          // 4096 tokens

// ---------------- scratch (device globals; no allocation allowed) ----------
__device__ float g_h  [TT*DD];           // residual stream
__device__ float g_x  [TT*DD];           // layernorm output / ao
__device__ float g_qkv[TT*3*DD];
__device__ float g_q  [TT*DD];           // [B*H, S, 64]
__device__ float g_k  [TT*DD];
__device__ float g_v  [TT*DD];
__device__ float g_sc [134217728];       // [B*H, S, S] scores, 536 MB
__device__ float g_o  [TT*DD];           // [B*H, S, 64]
__device__ float g_fc [TT*4*DD];

// ---------------- helpers ----------------
__device__ __forceinline__ float gelu_f(float x) {
    const float c = 0.7978845608028654f;  // sqrt(2/pi)
    float x3 = x * x * x;
    return 0.5f * x * (1.0f + tanhf(c * (x + 0.044715f * x3)));
}

// block-wide reduce for 256 threads (8 warps). ismax: max, else sum.
__device__ __forceinline__ float blk_red(float v, bool ismax) {
    __shared__ float sh[8];
    int lane = threadIdx.x & 31, wid = threadIdx.x >> 5;
    #pragma unroll
    for (int o = 16; o; o >>= 1) {
        float t = __shfl_xor_sync(0xffffffffu, v, o);
        v = ismax ? fmaxf(v, t) : v + t;
    }
    if (lane == 0) sh[wid] = v;
    __syncthreads();
    if (wid == 0) {
        float t = (lane < 8) ? sh[lane] : (ismax ? -3.4e38f : 0.0f);
        #pragma unroll
        for (int o = 4; o; o >>= 1) {
            float u = __shfl_xor_sync(0xffffffffu, t, o);
            t = ismax ? fmaxf(t, u) : t + u;
        }
        if (lane == 0) sh[0] = t;
    }
    __syncthreads();
    float r = sh[0];
    __syncthreads();   // protect sh[] reuse across successive calls
    return r;
}

// ---------------- embedding ----------------
__global__ void embed_k(const int* __restrict__ ids, const float* __restrict__ wte,
                        const float* __restrict__ wpe, float* __restrict__ h) {
    int t = blockIdx.x;
    int s = t % SS;
    int id = ids[t];
    const float4* w4 = (const float4*)(wte + (long)id * DD);
    const float4* p4 = (const float4*)(wpe + (long)s * DD);
    float4* h4 = (float4*)(h + (long)t * DD);
    int i = threadIdx.x;                  // 256 threads = DD/4
    float4 a = w4[i], b = p4[i];
    h4[i] = make_float4(a.x + b.x, a.y + b.y, a.z + b.z, a.w + b.w);
}

// ---------------- layernorm (row per block, 256 threads) ----------------
__global__ void ln_k(const float* __restrict__ in, const float* __restrict__ g,
                     const float* __restrict__ b, float* __restrict__ out) {
    int row = blockIdx.x;
    const float4* x4 = (const float4*)(in + (long)row * DD);
    int i = threadIdx.x;
    float4 v = x4[i];
    float s  = v.x + v.y + v.z + v.w;
    float sq = v.x * v.x + v.y * v.y + v.z * v.z + v.w * v.w;
    float tot  = blk_red(s, false);
    float totq = blk_red(sq, false);
    float mu  = tot * (1.0f / DD);
    float var = totq * (1.0f / DD) - mu * mu;
    float rstd = rsqrtf(var + 1e-5f);
    float4 gg = ((const float4*)g)[i];
    float4 bb = ((const float4*)b)[i];
    float4 r;
    r.x = (v.x - mu) * rstd * gg.x + bb.x;
    r.y = (v.y - mu) * rstd * gg.y + bb.y;
    r.z = (v.z - mu) * rstd * gg.z + bb.z;
    r.w = (v.w - mu) * rstd * gg.w + bb.w;
    ((float4*)(out + (long)row * DD))[i] = r;
}

// ---------------- qkv split to [B*H, S, 64] ----------------
__global__ void split_qkv_k(const float* __restrict__ qkv, float* __restrict__ q,
                            float* __restrict__ k, float* __restrict__ v) {
    int t = blockIdx.x;
    int b = t / SS, s = t % SS;
    const float* src = qkv + (long)t * 3 * DD;
    for (int c = threadIdx.x; c < DD; c += blockDim.x) {
        int h = c / HDD, d = c % HDD;
        long dst = ((long)(b * HH + h) * SS + s) * HDD + d;
        q[dst] = src[c];
        k[dst] = src[DD + c];
        v[dst] = src[2 * DD + c];
    }
}

// ---------------- merge heads back to [T, D] ----------------
__global__ void merge_o_k(const float* __restrict__ o, float* __restrict__ ao) {
    int t = blockIdx.x;
    int b = t / SS, s = t % SS;
    for (int c = threadIdx.x; c < DD; c += blockDim.x) {
        int h = c / HDD, d = c % HDD;
        ao[(long)t * DD + c] = o[((long)(b * HH + h) * SS + s) * HDD + d];
    }
}

// ---------------- causal softmax, row per block ----------------
__global__ void softmax_k(float* __restrict__ sc) {
    long row = blockIdx.x;               // over B*H*S
    int i = (int)(row % SS);
    float* p = sc + row * (long)SS;
    int tid = threadIdx.x;
    float mx = -3.4e38f;
    for (int j = tid; j <= i; j += 256) mx = fmaxf(mx, p[j]);
    float bmx = blk_red(mx, true);
    float sum = 0.0f;
    for (int j = tid; j <= i; j += 256) {
        float e = __expf(p[j] - bmx);
        p[j] = e;
        sum += e;
    }
    float bsum = blk_red(sum, false);
    float inv = 1.0f / bsum;
    for (int j = tid; j <= i; j += 256) p[j] *= inv;
    for (int j = i + 1 + tid; j < SS; j += 256) p[j] = 0.0f;
}

// ---------------- generic register-blocked SGEMM ----------------
// C[M,N] = alpha * A[M,K] @ op(B) (+ bias) (gelu?) (+ Cin)
// op(B): !TRANSB -> B is [K,N] row-major; TRANSB -> B is [N,K] row-major.
// Batched over blockIdx.z with element strides sA,sB,sC (bias/Cin non-batched).
template<int BM, int BN, int BK, int TM, int TN, bool TRANSB>
__global__ __launch_bounds__((BM / TM) * (BN / TN))
void gemm_k(const float* __restrict__ A, const float* __restrict__ Bm,
            const float* __restrict__ bias, const float* __restrict__ Cin,
            float* __restrict__ C,
            int M, int N, int K, int lda, int ldb, int ldc,
            long sA, long sB, long sC, float alpha, int do_gelu) {
    constexpr int NT = (BM / TM) * (BN / TN);
    __shared__ __align__(16) float As[BK][BM + 4];
    __shared__ __align__(16) float Bs[BK][BN + 4];

    A  += (long)blockIdx.z * sA;
    Bm += (long)blockIdx.z * sB;
    C  += (long)blockIdx.z * sC;

    int tid = threadIdx.x;
    int tx = tid % (BN / TN);
    int ty = tid / (BN / TN);
    int m0 = blockIdx.y * BM, n0 = blockIdx.x * BN;

    float acc[TM][TN];
    #pragma unroll
    for (int i = 0; i < TM; i++)
        #pragma unroll
        for (int j = 0; j < TN; j++) acc[i][j] = 0.0f;

    for (int k0 = 0; k0 < K; k0 += BK) {
        #pragma unroll
        for (int t = tid; t < BM * BK; t += NT) {
            int m = t / BK, kk = t - m * BK;
            int gm = m0 + m, gk = k0 + kk;
            As[kk][m] = (gm < M && gk < K) ? A[(long)gm * lda + gk] : 0.0f;
        }
        if (!TRANSB) {
            #pragma unroll
            for (int t = tid; t < BK * BN; t += NT) {
                int kk = t / BN, n = t - kk * BN;
                int gk = k0 + kk, gn = n0 + n;
                Bs[kk][n] = (gk < K && gn < N) ? Bm[(long)gk * ldb + gn] : 0.0f;
            }
        } else {
            #pragma unroll
            for (int t = tid; t < BK * BN; t += NT) {
                int n = t / BK, kk = t - n * BK;
                int gk = k0 + kk, gn = n0 + n;
                Bs[kk][n] = (gk < K && gn < N) ? Bm[(long)gn * ldb + gk] : 0.0f;
            }
        }
        __syncthreads();
        #pragma unroll
        for (int kk = 0; kk < BK; kk++) {
            float a[TM], b[TN];
            #pragma unroll
            for (int i = 0; i < TM; i += 4) {
                float4 va = *(const float4*)&As[kk][ty * TM + i];
                a[i] = va.x; a[i + 1] = va.y; a[i + 2] = va.z; a[i + 3] = va.w;
            }
            #pragma unroll
            for (int j = 0; j < TN; j += 4) {
                float4 vb = *(const float4*)&Bs[kk][tx * TN + j];
                b[j] = vb.x; b[j + 1] = vb.y; b[j + 2] = vb.z; b[j + 3] = vb.w;
            }
            #pragma unroll
            for (int i = 0; i < TM; i++)
                #pragma unroll
                for (int j = 0; j < TN; j++)
                    acc[i][j] = fmaf(a[i], b[j], acc[i][j]);
        }
        __syncthreads();
    }

    #pragma unroll
    for (int i = 0; i < TM; i++) {
        int gm = m0 + ty * TM + i;
        if (gm >= M) continue;
        #pragma unroll
        for (int j = 0; j < TN; j++) {
            int gn = n0 + tx * TN + j;
            if (gn >= N) continue;
            float r = acc[i][j] * alpha;
            if (bias) r += bias[gn];
            if (do_gelu) r = gelu_f(r);
            long idx = (long)gm * ldc + gn;
            if (Cin) r += Cin[idx];
            C[idx] = r;
        }
    }
}

// ---------------- launch ----------------
extern "C" void kernel_launch(void* const* d_in, const int* in_sizes, int n_in,
                              void* d_out, int out_size) {
    const int*   ids    = (const int*)  d_in[0];
    const float* wte    = (const float*)d_in[1];
    const float* wpe    = (const float*)d_in[2];
    const float* ln1_g  = (const float*)d_in[3];
    const float* ln1_b  = (const float*)d_in[4];
    const float* W_attn = (const float*)d_in[5];
    const float* b_attn = (const float*)d_in[6];
    const float* W_ap   = (const float*)d_in[7];
    const float* b_ap   = (const float*)d_in[8];
    const float* ln2_g  = (const float*)d_in[9];
    const float* ln2_b  = (const float*)d_in[10];
    const float* W_fc   = (const float*)d_in[11];
    const float* b_fc   = (const float*)d_in[12];
    const float* W_proj = (const float*)d_in[13];
    const float* b_proj = (const float*)d_in[14];
    const float* lnf_g  = (const float*)d_in[15];
    const float* lnf_b  = (const float*)d_in[16];
    const float* W_lm   = (const float*)d_in[17];
    float* out = (float*)d_out;

    float *h, *x, *qkv, *q, *k, *v, *sc, *o, *fc;
    cudaGetSymbolAddress((void**)&h,   g_h);
    cudaGetSymbolAddress((void**)&x,   g_x);
    cudaGetSymbolAddress((void**)&qkv, g_qkv);
    cudaGetSymbolAddress((void**)&q,   g_q);
    cudaGetSymbolAddress((void**)&k,   g_k);
    cudaGetSymbolAddress((void**)&v,   g_v);
    cudaGetSymbolAddress((void**)&sc,  g_sc);
    cudaGetSymbolAddress((void**)&o,   g_o);
    cudaGetSymbolAddress((void**)&fc,  g_fc);

    // 1. embeddings
    embed_k<<<TT, 256>>>(ids, wte, wpe, h);
    // 2. ln1
    ln_k<<<TT, 256>>>(h, ln1_g, ln1_b, x);
    // 3. qkv = x @ W_attn + b_attn    [4096, 3072]
    {
        dim3 g((3 * DD) / 128, TT / 128, 1);
        gemm_k<128, 128, 16, 8, 8, false><<<g, 256>>>(
            x, W_attn, b_attn, nullptr, qkv,
            TT, 3 * DD, DD, DD, 3 * DD, 3 * DD, 0, 0, 0, 1.0f, 0);
    }
    // 4. split heads
    split_qkv_k<<<TT, 256>>>(qkv, q, k, v);
    // 5. scores = (Q @ K^T) / 8, batched over B*H
    {
        dim3 g(SS / 128, SS / 128, BB * HH);
        gemm_k<128, 128, 16, 8, 8, true><<<g, 256>>>(
            q, k, nullptr, nullptr, sc,
            SS, SS, HDD, HDD, HDD, SS,
            (long)SS * HDD, (long)SS * HDD, (long)SS * SS, 0.125f, 0);
    }
    // 6. causal softmax in place
    softmax_k<<<BB * HH * SS, 256>>>(sc);
    // 7. O = P @ V, batched
    {
        dim3 g(1, SS / 128, BB * HH);
        gemm_k<128, 64, 16, 8, 4, false><<<g, 256>>>(
            sc, v, nullptr, nullptr, o,
            SS, HDD, SS, SS, HDD, HDD,
            (long)SS * SS, (long)SS * HDD, (long)SS * HDD, 1.0f, 0);
    }
    // 8. merge heads into x (reused as ao)
    merge_o_k<<<TT, 256>>>(o, x);
    // 9. h = h + ao @ W_ap + b_ap
    {
        dim3 g(DD / 128, TT / 128, 1);
        gemm_k<128, 128, 16, 8, 8, false><<<g, 256>>>(
            x, W_ap, b_ap, h, h,
            TT, DD, DD, DD, DD, DD, 0, 0, 0, 1.0f, 0);
    }
    // 10. ln2
    ln_k<<<TT, 256>>>(h, ln2_g, ln2_b, x);
    // 11. fc = gelu(x @ W_fc + b_fc)  [4096, 4096]
    {
        dim3 g((4 * DD) / 128, TT / 128, 1);
        gemm_k<128, 128, 16, 8, 8, false><<<g, 256>>>(
            x, W_fc, b_fc, nullptr, fc,
            TT, 4 * DD, DD, DD, 4 * DD, 4 * DD, 0, 0, 0, 1.0f, 1);
    }
    // 12. h = h + fc @ W_proj + b_proj
    {
        dim3 g(DD / 128, TT / 128, 1);
        gemm_k<128, 128, 16, 8, 8, false><<<g, 256>>>(
            fc, W_proj, b_proj, h, h,
            TT, DD, 4 * DD, 4 * DD, DD, DD, 0, 0, 0, 1.0f, 0);
    }
    // 13. lnf
    ln_k<<<TT, 256>>>(h, lnf_g, lnf_b, x);
    // 14. logits = x @ W_lm   [4096, 50257]
    {
        dim3 g((VV + 127) / 128, TT / 128, 1);
        gemm_k<128, 128, 16, 8, 8, false><<<g, 256>>>(
            x, W_lm, nullptr, nullptr, out,
            TT, VV, DD, DD, VV, VV, 0, 0, 0, 1.0f, 0);
    }
}

// round 6
// speedup vs baseline: 2.6089x; 2.6089x over previous
#include <cuda_runtime.h>
#include <math.h>
#include <stdint.h>

// Problem constants
#define BB 2
#define SS 2048
#define DD 1024
#define HH 16
#define HDD 64
#define VV 50257
#define TT (BB*SS)          // 4096 tokens

// ---------------- scratch (device globals; no allocation allowed) ----------
__device__ float g_h  [TT*DD];           // residual stream
__device__ float g_x  [TT*DD];           // layernorm output / ao
__device__ float g_qkv[TT*3*DD];
__device__ float g_q  [TT*DD];           // [B*H, S, 64]
__device__ float g_k  [TT*DD];
__device__ float g_v  [TT*DD];
__device__ float g_sc [134217728];       // [B*H, S, S] scores, 536 MB
__device__ float g_o  [TT*DD];           // [B*H, S, 64]
__device__ float g_fc [TT*4*DD];

// ---------------- helpers ----------------
__device__ __forceinline__ float gelu_f(float x) {
    const float c = 0.7978845608028654f;  // sqrt(2/pi)
    float x3 = x * x * x;
    return 0.5f * x * (1.0f + tanhf(c * (x + 0.044715f * x3)));
}

__device__ __forceinline__ uint32_t f2tf(float f) {
    uint32_t r;
    asm("cvt.rna.tf32.f32 %0, %1;" : "=r"(r) : "f"(f));
    return r;
}

__device__ __forceinline__ void cp16(void* smem_dst, const void* gmem_src) {
    uint32_t s = (uint32_t)__cvta_generic_to_shared(smem_dst);
    asm volatile("cp.async.cg.shared.global [%0], [%1], 16;\n" :: "r"(s), "l"(gmem_src));
}
__device__ __forceinline__ void cp_commit() {
    asm volatile("cp.async.commit_group;\n");
}
template<int N>
__device__ __forceinline__ void cp_wait() {
    asm volatile("cp.async.wait_group %0;\n" :: "n"(N));
}

__device__ __forceinline__ void mma_tf32(float c[4], const uint32_t a[4], const uint32_t b[2]) {
    asm volatile(
        "mma.sync.aligned.m16n8k8.row.col.f32.tf32.tf32.f32 "
        "{%0,%1,%2,%3}, {%4,%5,%6,%7}, {%8,%9}, {%0,%1,%2,%3};"
        : "+f"(c[0]), "+f"(c[1]), "+f"(c[2]), "+f"(c[3])
        : "r"(a[0]), "r"(a[1]), "r"(a[2]), "r"(a[3]), "r"(b[0]), "r"(b[1]));
}

// block-wide reduce for 256 threads (8 warps). ismax: max, else sum.
__device__ __forceinline__ float blk_red(float v, bool ismax) {
    __shared__ float sh[8];
    int lane = threadIdx.x & 31, wid = threadIdx.x >> 5;
    #pragma unroll
    for (int o = 16; o; o >>= 1) {
        float t = __shfl_xor_sync(0xffffffffu, v, o);
        v = ismax ? fmaxf(v, t) : v + t;
    }
    if (lane == 0) sh[wid] = v;
    __syncthreads();
    if (wid == 0) {
        float t = (lane < 8) ? sh[lane] : (ismax ? -3.4e38f : 0.0f);
        #pragma unroll
        for (int o = 4; o; o >>= 1) {
            float u = __shfl_xor_sync(0xffffffffu, t, o);
            t = ismax ? fmaxf(t, u) : t + u;
        }
        if (lane == 0) sh[0] = t;
    }
    __syncthreads();
    float r = sh[0];
    __syncthreads();
    return r;
}

// ---------------- embedding ----------------
__global__ void embed_k(const int* __restrict__ ids, const float* __restrict__ wte,
                        const float* __restrict__ wpe, float* __restrict__ h) {
    int t = blockIdx.x;
    int s = t % SS;
    int id = ids[t];
    const float4* w4 = (const float4*)(wte + (long)id * DD);
    const float4* p4 = (const float4*)(wpe + (long)s * DD);
    float4* h4 = (float4*)(h + (long)t * DD);
    int i = threadIdx.x;
    float4 a = w4[i], b = p4[i];
    h4[i] = make_float4(a.x + b.x, a.y + b.y, a.z + b.z, a.w + b.w);
}

// ---------------- layernorm ----------------
__global__ void ln_k(const float* __restrict__ in, const float* __restrict__ g,
                     const float* __restrict__ b, float* __restrict__ out) {
    int row = blockIdx.x;
    const float4* x4 = (const float4*)(in + (long)row * DD);
    int i = threadIdx.x;
    float4 v = x4[i];
    float s  = v.x + v.y + v.z + v.w;
    float sq = v.x * v.x + v.y * v.y + v.z * v.z + v.w * v.w;
    float tot  = blk_red(s, false);
    float totq = blk_red(sq, false);
    float mu  = tot * (1.0f / DD);
    float var = totq * (1.0f / DD) - mu * mu;
    float rstd = rsqrtf(var + 1e-5f);
    float4 gg = ((const float4*)g)[i];
    float4 bb = ((const float4*)b)[i];
    float4 r;
    r.x = (v.x - mu) * rstd * gg.x + bb.x;
    r.y = (v.y - mu) * rstd * gg.y + bb.y;
    r.z = (v.z - mu) * rstd * gg.z + bb.z;
    r.w = (v.w - mu) * rstd * gg.w + bb.w;
    ((float4*)(out + (long)row * DD))[i] = r;
}

// ---------------- qkv split to [B*H, S, 64] ----------------
__global__ void split_qkv_k(const float* __restrict__ qkv, float* __restrict__ q,
                            float* __restrict__ k, float* __restrict__ v) {
    int t = blockIdx.x;
    int b = t / SS, s = t % SS;
    const float* src = qkv + (long)t * 3 * DD;
    for (int c = threadIdx.x; c < DD; c += blockDim.x) {
        int h = c / HDD, d = c % HDD;
        long dst = ((long)(b * HH + h) * SS + s) * HDD + d;
        q[dst] = src[c];
        k[dst] = src[DD + c];
        v[dst] = src[2 * DD + c];
    }
}

// ---------------- merge heads back to [T, D] ----------------
__global__ void merge_o_k(const float* __restrict__ o, float* __restrict__ ao) {
    int t = blockIdx.x;
    int b = t / SS, s = t % SS;
    for (int c = threadIdx.x; c < DD; c += blockDim.x) {
        int h = c / HDD, d = c % HDD;
        ao[(long)t * DD + c] = o[((long)(b * HH + h) * SS + s) * HDD + d];
    }
}

// ---------------- causal softmax, row per block ----------------
__global__ void softmax_k(float* __restrict__ sc) {
    long row = blockIdx.x;               // over B*H*S
    int i = (int)(row % SS);
    float* p = sc + row * (long)SS;
    int tid = threadIdx.x;
    float mx = -3.4e38f;
    for (int j = tid; j <= i; j += 256) mx = fmaxf(mx, p[j]);
    float bmx = blk_red(mx, true);
    float sum = 0.0f;
    for (int j = tid; j <= i; j += 256) {
        float e = __expf(p[j] - bmx);
        p[j] = e;
        sum += e;
    }
    float bsum = blk_red(sum, false);
    float inv = 1.0f / bsum;
    for (int j = tid; j <= i; j += 256) p[j] *= inv;
    for (int j = i + 1 + tid; j < SS; j += 256) p[j] = 0.0f;
}

// ---------------- TF32 tensor-core GEMM ----------------
// C[M,N] = alpha * A[M,K] @ op(B) (+bias)(gelu?)(+Cin)
// !TRANSB: B is [K,N] row-major.  TRANSB: B is [N,K] row-major (C = A @ B^T).
// ALIGNED_B: B rows are 16B-aligned (ldb % 4 == 0 and base 16B-aligned) ->
//            cp.async loads. Otherwise scalar 4B loads (e.g. W_lm, ldb=50257).
// Batched over blockIdx.z with element strides sA,sB,sC.
// Requires: M % BM == 0, K % BK == 0. N edge handled.
template<int BM, int BN, int BK, int WM, int WN, bool TRANSB, bool ALIGNED_B>
__global__ __launch_bounds__((BM / WM) * (BN / WN) * 32)
void gemm_tc(const float* __restrict__ A, const float* __restrict__ Bm,
             const float* __restrict__ bias, const float* __restrict__ Cin,
             float* __restrict__ C,
             int M, int N, int K, int lda, int ldb, int ldc,
             long sA, long sB, long sC, float alpha, int do_gelu) {
    constexpr int WARPS_M = BM / WM;
    constexpr int WARPS_N = BN / WN;
    constexpr int NWARP = WARPS_M * WARPS_N;
    constexpr int NTHREADS = NWARP * 32;
    constexpr int MT = WM / 16;
    constexpr int NT = WN / 8;
    constexpr int AS_STRIDE = BK + 4;                    // 20: conflict-free frag loads
    constexpr int BS_ROWS   = TRANSB ? BN : BK;
    constexpr int BS_STRIDE = TRANSB ? (BK + 4) : (BN + 8);

    __shared__ __align__(16) float As[2][BM][AS_STRIDE];
    __shared__ __align__(16) float Bs[2][BS_ROWS][BS_STRIDE];

    A  += (long)blockIdx.z * sA;
    Bm += (long)blockIdx.z * sB;
    C  += (long)blockIdx.z * sC;

    const int tid = threadIdx.x;
    const int lane = tid & 31;
    const int wid = tid >> 5;
    const int wm = wid % WARPS_M;
    const int wn = wid / WARPS_M;
    const int g = lane >> 2;           // group id 0..7
    const int c = lane & 3;            // thread-in-group 0..3
    const int m0 = blockIdx.y * BM;
    const int n0 = blockIdx.x * BN;

    float acc[MT][NT][4];
    #pragma unroll
    for (int i = 0; i < MT; i++)
        #pragma unroll
        for (int j = 0; j < NT; j++)
            #pragma unroll
            for (int e = 0; e < 4; e++) acc[i][j][e] = 0.0f;

    // --- tile loader ---
    auto load_tile = [&](int i, int buf) {
        int k0 = i * BK;
        // A: BM x BK, always in-bounds & aligned (M,K multiples; lda % 4 == 0)
        #pragma unroll 2
        for (int v = tid; v < BM * (BK / 4); v += NTHREADS) {
            int m  = v / (BK / 4);
            int kv = v % (BK / 4);
            cp16(&As[buf][m][kv * 4], A + (long)(m0 + m) * lda + (k0 + kv * 4));
        }
        if (!TRANSB) {
            if (ALIGNED_B) {
                #pragma unroll 2
                for (int v = tid; v < BK * (BN / 4); v += NTHREADS) {
                    int kk = v / (BN / 4);
                    int nv = v % (BN / 4);
                    int gn = n0 + nv * 4;
                    float* dst = &Bs[buf][kk][nv * 4];
                    const float* src = Bm + (long)(k0 + kk) * ldb + gn;
                    if (gn + 3 < N) {
                        cp16(dst, src);
                    } else {
                        #pragma unroll
                        for (int j = 0; j < 4; j++)
                            dst[j] = (gn + j < N) ? src[j] : 0.0f;
                    }
                }
            } else {
                // scalar path: 4B loads, coalesced across consecutive tid
                #pragma unroll 4
                for (int v = tid; v < BK * BN; v += NTHREADS) {
                    int kk = v / BN;
                    int n  = v % BN;
                    int gn = n0 + n;
                    Bs[buf][kk][n] = (gn < N)
                        ? __ldg(Bm + (long)(k0 + kk) * ldb + gn) : 0.0f;
                }
            }
        } else {
            #pragma unroll 2
            for (int v = tid; v < BN * (BK / 4); v += NTHREADS) {
                int n  = v / (BK / 4);
                int kv = v % (BK / 4);
                cp16(&Bs[buf][n][kv * 4], Bm + (long)(n0 + n) * ldb + (k0 + kv * 4));
            }
        }
        cp_commit();
    };

    const int nk = K / BK;
    load_tile(0, 0);
    int buf = 0;

    for (int i = 0; i < nk; i++) {
        if (i + 1 < nk) load_tile(i + 1, buf ^ 1);
        else            cp_commit();          // empty group keeps wait count uniform
        cp_wait<1>();
        __syncthreads();

        #pragma unroll
        for (int ks = 0; ks < BK / 8; ks++) {
            uint32_t af[MT][4];
            uint32_t bf[NT][2];
            #pragma unroll
            for (int mt = 0; mt < MT; mt++) {
                int mr = wm * WM + mt * 16;
                af[mt][0] = f2tf(As[buf][mr + g    ][ks * 8 + c]);
                af[mt][1] = f2tf(As[buf][mr + g + 8][ks * 8 + c]);
                af[mt][2] = f2tf(As[buf][mr + g    ][ks * 8 + c + 4]);
                af[mt][3] = f2tf(As[buf][mr + g + 8][ks * 8 + c + 4]);
            }
            #pragma unroll
            for (int nt = 0; nt < NT; nt++) {
                int nc = wn * WN + nt * 8 + g;
                if (!TRANSB) {
                    bf[nt][0] = f2tf(Bs[buf][ks * 8 + c    ][nc]);
                    bf[nt][1] = f2tf(Bs[buf][ks * 8 + c + 4][nc]);
                } else {
                    bf[nt][0] = f2tf(Bs[buf][nc][ks * 8 + c]);
                    bf[nt][1] = f2tf(Bs[buf][nc][ks * 8 + c + 4]);
                }
            }
            #pragma unroll
            for (int mt = 0; mt < MT; mt++)
                #pragma unroll
                for (int nt = 0; nt < NT; nt++)
                    mma_tf32(acc[mt][nt], af[mt], bf[nt]);
        }

        buf ^= 1;
        __syncthreads();
    }

    // --- epilogue ---
    #pragma unroll
    for (int mt = 0; mt < MT; mt++) {
        #pragma unroll
        for (int nt = 0; nt < NT; nt++) {
            int gn0 = n0 + wn * WN + nt * 8 + c * 2;
            #pragma unroll
            for (int half = 0; half < 2; half++) {
                int gm = m0 + wm * WM + mt * 16 + g + half * 8;
                float v0 = acc[mt][nt][half * 2 + 0] * alpha;
                float v1 = acc[mt][nt][half * 2 + 1] * alpha;
                if (bias) {
                    if (gn0 < N)     v0 += bias[gn0];
                    if (gn0 + 1 < N) v1 += bias[gn0 + 1];
                }
                if (do_gelu) { v0 = gelu_f(v0); v1 = gelu_f(v1); }
                long idx = (long)gm * ldc + gn0;
                if (Cin) {
                    if (gn0 < N)     v0 += Cin[idx];
                    if (gn0 + 1 < N) v1 += Cin[idx + 1];
                }
                if (gn0 + 1 < N) {
                    C[idx]     = v0;
                    C[idx + 1] = v1;
                } else if (gn0 < N) {
                    C[idx] = v0;
                }
            }
        }
    }
}

// ---------------- launch ----------------
extern "C" void kernel_launch(void* const* d_in, const int* in_sizes, int n_in,
                              void* d_out, int out_size) {
    const int*   ids    = (const int*)  d_in[0];
    const float* wte    = (const float*)d_in[1];
    const float* wpe    = (const float*)d_in[2];
    const float* ln1_g  = (const float*)d_in[3];
    const float* ln1_b  = (const float*)d_in[4];
    const float* W_attn = (const float*)d_in[5];
    const float* b_attn = (const float*)d_in[6];
    const float* W_ap   = (const float*)d_in[7];
    const float* b_ap   = (const float*)d_in[8];
    const float* ln2_g  = (const float*)d_in[9];
    const float* ln2_b  = (const float*)d_in[10];
    const float* W_fc   = (const float*)d_in[11];
    const float* b_fc   = (const float*)d_in[12];
    const float* W_proj = (const float*)d_in[13];
    const float* b_proj = (const float*)d_in[14];
    const float* lnf_g  = (const float*)d_in[15];
    const float* lnf_b  = (const float*)d_in[16];
    const float* W_lm   = (const float*)d_in[17];
    float* out = (float*)d_out;

    float *h, *x, *qkv, *q, *k, *v, *sc, *o, *fc;
    cudaGetSymbolAddress((void**)&h,   g_h);
    cudaGetSymbolAddress((void**)&x,   g_x);
    cudaGetSymbolAddress((void**)&qkv, g_qkv);
    cudaGetSymbolAddress((void**)&q,   g_q);
    cudaGetSymbolAddress((void**)&k,   g_k);
    cudaGetSymbolAddress((void**)&v,   g_v);
    cudaGetSymbolAddress((void**)&sc,  g_sc);
    cudaGetSymbolAddress((void**)&o,   g_o);
    cudaGetSymbolAddress((void**)&fc,  g_fc);

    // 1. embeddings
    embed_k<<<TT, 256>>>(ids, wte, wpe, h);
    // 2. ln1
    ln_k<<<TT, 256>>>(h, ln1_g, ln1_b, x);
    // 3. qkv = x @ W_attn + b_attn    [4096, 3072]
    {
        dim3 grd((3 * DD) / 128, TT / 128, 1);
        gemm_tc<128, 128, 16, 64, 32, false, true><<<grd, 256>>>(
            x, W_attn, b_attn, nullptr, qkv,
            TT, 3 * DD, DD, DD, 3 * DD, 3 * DD, 0, 0, 0, 1.0f, 0);
    }
    // 4. split heads
    split_qkv_k<<<TT, 256>>>(qkv, q, k, v);
    // 5. scores = (Q @ K^T) / 8, batched over B*H
    {
        dim3 grd(SS / 128, SS / 128, BB * HH);
        gemm_tc<128, 128, 16, 64, 32, true, true><<<grd, 256>>>(
            q, k, nullptr, nullptr, sc,
            SS, SS, HDD, HDD, HDD, SS,
            (long)SS * HDD, (long)SS * HDD, (long)SS * SS, 0.125f, 0);
    }
    // 6. causal softmax in place
    softmax_k<<<BB * HH * SS, 256>>>(sc);
    // 7. O = P @ V, batched
    {
        dim3 grd(1, SS / 128, BB * HH);
        gemm_tc<128, 64, 16, 64, 16, false, true><<<grd, 256>>>(
            sc, v, nullptr, nullptr, o,
            SS, HDD, SS, SS, HDD, HDD,
            (long)SS * SS, (long)SS * HDD, (long)SS * HDD, 1.0f, 0);
    }
    // 8. merge heads into x (reused as ao)
    merge_o_k<<<TT, 256>>>(o, x);
    // 9. h = h + ao @ W_ap + b_ap
    {
        dim3 grd(DD / 128, TT / 128, 1);
        gemm_tc<128, 128, 16, 64, 32, false, true><<<grd, 256>>>(
            x, W_ap, b_ap, h, h,
            TT, DD, DD, DD, DD, DD, 0, 0, 0, 1.0f, 0);
    }
    // 10. ln2
    ln_k<<<TT, 256>>>(h, ln2_g, ln2_b, x);
    // 11. fc = gelu(x @ W_fc + b_fc)  [4096, 4096]
    {
        dim3 grd((4 * DD) / 128, TT / 128, 1);
        gemm_tc<128, 128, 16, 64, 32, false, true><<<grd, 256>>>(
            x, W_fc, b_fc, nullptr, fc,
            TT, 4 * DD, DD, DD, 4 * DD, 4 * DD, 0, 0, 0, 1.0f, 1);
    }
    // 12. h = h + fc @ W_proj + b_proj
    {
        dim3 grd(DD / 128, TT / 128, 1);
        gemm_tc<128, 128, 16, 64, 32, false, true><<<grd, 256>>>(
            fc, W_proj, b_proj, h, h,
            TT, DD, 4 * DD, 4 * DD, DD, DD, 0, 0, 0, 1.0f, 0);
    }
    // 13. lnf
    ln_k<<<TT, 256>>>(h, lnf_g, lnf_b, x);
    // 14. logits = x @ W_lm   [4096, 50257]  (ldb=50257 is odd -> unaligned B)
    {
        dim3 grd((VV + 127) / 128, TT / 128, 1);
        gemm_tc<128, 128, 16, 64, 32, false, false><<<grd, 256>>>(
            x, W_lm, nullptr, nullptr, out,
            TT, VV, DD, DD, VV, VV, 0, 0, 0, 1.0f, 0);
    }
}

// round 8
// speedup vs baseline: 2.9589x; 1.1342x over previous
#include <cuda_runtime.h>
#include <math.h>
#include <stdint.h>

// Problem constants
#define BB 2
#define SS 2048
#define DD 1024
#define HH 16
#define HDD 64
#define VV 50257
#define TT (BB*SS)          // 4096 tokens

// ---------------- scratch (device globals; no allocation allowed) ----------
__device__ float g_h  [TT*DD];           // residual stream
__device__ float g_x  [TT*DD];           // layernorm output / ao
__device__ float g_qkv[TT*3*DD];
__device__ float g_q  [TT*DD];           // [B*H, S, 64]
__device__ float g_k  [TT*DD];
__device__ float g_v  [TT*DD];
__device__ float g_sc [134217728];       // [B*H, S, S] scores, 536 MB
__device__ float g_o  [TT*DD];           // [B*H, S, 64]
__device__ float g_fc [TT*4*DD];

// ---------------- helpers ----------------
__device__ __forceinline__ float gelu_f(float x) {
    const float c = 0.7978845608028654f;  // sqrt(2/pi)
    float x3 = x * x * x;
    return 0.5f * x * (1.0f + tanhf(c * (x + 0.044715f * x3)));
}

__device__ __forceinline__ uint32_t f2tf(float f) {
    uint32_t r;
    asm("cvt.rna.tf32.f32 %0, %1;" : "=r"(r) : "f"(f));
    return r;
}

__device__ __forceinline__ void cp16(void* smem_dst, const void* gmem_src) {
    uint32_t s = (uint32_t)__cvta_generic_to_shared(smem_dst);
    asm volatile("cp.async.cg.shared.global [%0], [%1], 16;\n" :: "r"(s), "l"(gmem_src));
}
__device__ __forceinline__ void cp_commit() {
    asm volatile("cp.async.commit_group;\n");
}
template<int N>
__device__ __forceinline__ void cp_wait() {
    asm volatile("cp.async.wait_group %0;\n" :: "n"(N));
}

__device__ __forceinline__ void mma_tf32(float c[4], const uint32_t a[4], const uint32_t b[2]) {
    asm volatile(
        "mma.sync.aligned.m16n8k8.row.col.f32.tf32.tf32.f32 "
        "{%0,%1,%2,%3}, {%4,%5,%6,%7}, {%8,%9}, {%0,%1,%2,%3};"
        : "+f"(c[0]), "+f"(c[1]), "+f"(c[2]), "+f"(c[3])
        : "r"(a[0]), "r"(a[1]), "r"(a[2]), "r"(a[3]), "r"(b[0]), "r"(b[1]));
}

// block-wide reduce for 256 threads (8 warps). ismax: max, else sum.
__device__ __forceinline__ float blk_red(float v, bool ismax) {
    __shared__ float sh[8];
    int lane = threadIdx.x & 31, wid = threadIdx.x >> 5;
    #pragma unroll
    for (int o = 16; o; o >>= 1) {
        float t = __shfl_xor_sync(0xffffffffu, v, o);
        v = ismax ? fmaxf(v, t) : v + t;
    }
    if (lane == 0) sh[wid] = v;
    __syncthreads();
    if (wid == 0) {
        float t = (lane < 8) ? sh[lane] : (ismax ? -3.4e38f : 0.0f);
        #pragma unroll
        for (int o = 4; o; o >>= 1) {
            float u = __shfl_xor_sync(0xffffffffu, t, o);
            t = ismax ? fmaxf(t, u) : t + u;
        }
        if (lane == 0) sh[0] = t;
    }
    __syncthreads();
    float r = sh[0];
    __syncthreads();
    return r;
}

// ---------------- embedding ----------------
__global__ void embed_k(const int* __restrict__ ids, const float* __restrict__ wte,
                        const float* __restrict__ wpe, float* __restrict__ h) {
    int t = blockIdx.x;
    int s = t % SS;
    int id = ids[t];
    const float4* w4 = (const float4*)(wte + (long)id * DD);
    const float4* p4 = (const float4*)(wpe + (long)s * DD);
    float4* h4 = (float4*)(h + (long)t * DD);
    int i = threadIdx.x;
    float4 a = w4[i], b = p4[i];
    h4[i] = make_float4(a.x + b.x, a.y + b.y, a.z + b.z, a.w + b.w);
}

// ---------------- layernorm ----------------
__global__ void ln_k(const float* __restrict__ in, const float* __restrict__ g,
                     const float* __restrict__ b, float* __restrict__ out) {
    int row = blockIdx.x;
    const float4* x4 = (const float4*)(in + (long)row * DD);
    int i = threadIdx.x;
    float4 v = x4[i];
    float s  = v.x + v.y + v.z + v.w;
    float sq = v.x * v.x + v.y * v.y + v.z * v.z + v.w * v.w;
    float tot  = blk_red(s, false);
    float totq = blk_red(sq, false);
    float mu  = tot * (1.0f / DD);
    float var = totq * (1.0f / DD) - mu * mu;
    float rstd = rsqrtf(var + 1e-5f);
    float4 gg = ((const float4*)g)[i];
    float4 bb = ((const float4*)b)[i];
    float4 r;
    r.x = (v.x - mu) * rstd * gg.x + bb.x;
    r.y = (v.y - mu) * rstd * gg.y + bb.y;
    r.z = (v.z - mu) * rstd * gg.z + bb.z;
    r.w = (v.w - mu) * rstd * gg.w + bb.w;
    ((float4*)(out + (long)row * DD))[i] = r;
}

// ---------------- qkv split to [B*H, S, 64] ----------------
__global__ void split_qkv_k(const float* __restrict__ qkv, float* __restrict__ q,
                            float* __restrict__ k, float* __restrict__ v) {
    int t = blockIdx.x;
    int b = t / SS, s = t % SS;
    const float* src = qkv + (long)t * 3 * DD;
    for (int c = threadIdx.x; c < DD; c += blockDim.x) {
        int h = c / HDD, d = c % HDD;
        long dst = ((long)(b * HH + h) * SS + s) * HDD + d;
        q[dst] = src[c];
        k[dst] = src[DD + c];
        v[dst] = src[2 * DD + c];
    }
}

// ---------------- merge heads back to [T, D] ----------------
__global__ void merge_o_k(const float* __restrict__ o, float* __restrict__ ao) {
    int t = blockIdx.x;
    int b = t / SS, s = t % SS;
    for (int c = threadIdx.x; c < DD; c += blockDim.x) {
        int h = c / HDD, d = c % HDD;
        ao[(long)t * DD + c] = o[((long)(b * HH + h) * SS + s) * HDD + d];
    }
}

// ---------------- causal softmax, row per block ----------------
// PV limits K to the 128-row block boundary, so zero-fill only up to there.
__global__ void softmax_k(float* __restrict__ sc) {
    long row = blockIdx.x;               // over B*H*S
    int i = (int)(row % SS);
    float* p = sc + row * (long)SS;
    int tid = threadIdx.x;
    float mx = -3.4e38f;
    for (int j = tid; j <= i; j += 256) mx = fmaxf(mx, p[j]);
    float bmx = blk_red(mx, true);
    float sum = 0.0f;
    for (int j = tid; j <= i; j += 256) {
        float e = __expf(p[j] - bmx);
        p[j] = e;
        sum += e;
    }
    float bsum = blk_red(sum, false);
    float inv = 1.0f / bsum;
    for (int j = tid; j <= i; j += 256) p[j] *= inv;
    int jlim = ((i >> 7) + 1) << 7;       // next multiple of 128 (PV K-limit)
    for (int j = i + 1 + tid; j < jlim; j += 256) p[j] = 0.0f;
}

// ---------------- TF32 tensor-core GEMM ----------------
// C[M,N] = alpha * A[M,K] @ op(B) (+bias)(gelu?)(+Cin)
// !TRANSB: B is [K,N] row-major.  TRANSB: B is [N,K] row-major (C = A @ B^T).
// ALIGNED_B: B rows 16B-aligned -> cp.async; else scalar 4B loads (W_lm).
// SWAPXY: blockIdx.x indexes M, blockIdx.y indexes N (L2 reuse for huge N).
// causal: 0 none; 1 = skip blocks with n0 > m0 (scores); 2 = limit K to m0+BM (PV).
// Batched over blockIdx.z. Requires M % BM == 0, K % BK == 0. N edge handled.
template<int BM, int BN, int BK, int WM, int WN, bool TRANSB, bool ALIGNED_B, bool SWAPXY>
__global__ __launch_bounds__((BM / WM) * (BN / WN) * 32)
void gemm_tc(const float* __restrict__ A, const float* __restrict__ Bm,
             const float* __restrict__ bias, const float* __restrict__ Cin,
             float* __restrict__ C,
             int M, int N, int K, int lda, int ldb, int ldc,
             long sA, long sB, long sC, float alpha, int do_gelu, int causal) {
    constexpr int WARPS_M = BM / WM;
    constexpr int WARPS_N = BN / WN;
    constexpr int NWARP = WARPS_M * WARPS_N;
    constexpr int NTHREADS = NWARP * 32;
    constexpr int MT = WM / 16;
    constexpr int NT = WN / 8;
    constexpr int AS_STRIDE = BK + 4;
    constexpr int BS_ROWS   = TRANSB ? BN : BK;
    constexpr int BS_STRIDE = TRANSB ? (BK + 4) : (BN + 8);

    __shared__ __align__(16) float As[2][BM][AS_STRIDE];
    __shared__ __align__(16) float Bs[2][BS_ROWS][BS_STRIDE];

    const int m0 = (SWAPXY ? blockIdx.x : blockIdx.y) * BM;
    const int n0 = (SWAPXY ? blockIdx.y : blockIdx.x) * BN;
    if (causal == 1 && n0 > m0) return;            // fully-masked score block

    A  += (long)blockIdx.z * sA;
    Bm += (long)blockIdx.z * sB;
    C  += (long)blockIdx.z * sC;

    const int tid = threadIdx.x;
    const int lane = tid & 31;
    const int wid = tid >> 5;
    const int wm = wid % WARPS_M;
    const int wn = wid / WARPS_M;
    const int g = lane >> 2;           // group id 0..7
    const int c = lane & 3;            // thread-in-group 0..3

    float acc[MT][NT][4];
    #pragma unroll
    for (int i = 0; i < MT; i++)
        #pragma unroll
        for (int j = 0; j < NT; j++)
            #pragma unroll
            for (int e = 0; e < 4; e++) acc[i][j][e] = 0.0f;

    // --- tile loader ---
    auto load_tile = [&](int i, int buf) {
        int k0 = i * BK;
        #pragma unroll 2
        for (int v = tid; v < BM * (BK / 4); v += NTHREADS) {
            int m  = v / (BK / 4);
            int kv = v % (BK / 4);
            cp16(&As[buf][m][kv * 4], A + (long)(m0 + m) * lda + (k0 + kv * 4));
        }
        if (!TRANSB) {
            if (ALIGNED_B) {
                #pragma unroll 2
                for (int v = tid; v < BK * (BN / 4); v += NTHREADS) {
                    int kk = v / (BN / 4);
                    int nv = v % (BN / 4);
                    int gn = n0 + nv * 4;
                    float* dst = &Bs[buf][kk][nv * 4];
                    const float* src = Bm + (long)(k0 + kk) * ldb + gn;
                    if (gn + 3 < N) {
                        cp16(dst, src);
                    } else {
                        #pragma unroll
                        for (int j = 0; j < 4; j++)
                            dst[j] = (gn + j < N) ? src[j] : 0.0f;
                    }
                }
            } else {
                #pragma unroll 4
                for (int v = tid; v < BK * BN; v += NTHREADS) {
                    int kk = v / BN;
                    int n  = v % BN;
                    int gn = n0 + n;
                    Bs[buf][kk][n] = (gn < N)
                        ? __ldg(Bm + (long)(k0 + kk) * ldb + gn) : 0.0f;
                }
            }
        } else {
            #pragma unroll 2
            for (int v = tid; v < BN * (BK / 4); v += NTHREADS) {
                int n  = v / (BK / 4);
                int kv = v % (BK / 4);
                cp16(&Bs[buf][n][kv * 4], Bm + (long)(n0 + n) * ldb + (k0 + kv * 4));
            }
        }
        cp_commit();
    };

    const int Keff = (causal == 2) ? min(K, m0 + BM) : K;
    const int nk = Keff / BK;
    load_tile(0, 0);
    int buf = 0;

    for (int i = 0; i < nk; i++) {
        if (i + 1 < nk) load_tile(i + 1, buf ^ 1);
        else            cp_commit();          // empty group keeps wait count uniform
        cp_wait<1>();
        __syncthreads();

        #pragma unroll
        for (int ks = 0; ks < BK / 8; ks++) {
            uint32_t af[MT][4];
            uint32_t bf[NT][2];
            #pragma unroll
            for (int mt = 0; mt < MT; mt++) {
                int mr = wm * WM + mt * 16;
                af[mt][0] = f2tf(As[buf][mr + g    ][ks * 8 + c]);
                af[mt][1] = f2tf(As[buf][mr + g + 8][ks * 8 + c]);
                af[mt][2] = f2tf(As[buf][mr + g    ][ks * 8 + c + 4]);
                af[mt][3] = f2tf(As[buf][mr + g + 8][ks * 8 + c + 4]);
            }
            #pragma unroll
            for (int nt = 0; nt < NT; nt++) {
                int nc = wn * WN + nt * 8 + g;
                if (!TRANSB) {
                    bf[nt][0] = f2tf(Bs[buf][ks * 8 + c    ][nc]);
                    bf[nt][1] = f2tf(Bs[buf][ks * 8 + c + 4][nc]);
                } else {
                    bf[nt][0] = f2tf(Bs[buf][nc][ks * 8 + c]);
                    bf[nt][1] = f2tf(Bs[buf][nc][ks * 8 + c + 4]);
                }
            }
            #pragma unroll
            for (int mt = 0; mt < MT; mt++)
                #pragma unroll
                for (int nt = 0; nt < NT; nt++)
                    mma_tf32(acc[mt][nt], af[mt], bf[nt]);
        }

        buf ^= 1;
        __syncthreads();
    }

    // --- epilogue ---
    #pragma unroll
    for (int mt = 0; mt < MT; mt++) {
        #pragma unroll
        for (int nt = 0; nt < NT; nt++) {
            int gn0 = n0 + wn * WN + nt * 8 + c * 2;
            #pragma unroll
            for (int half = 0; half < 2; half++) {
                int gm = m0 + wm * WM + mt * 16 + g + half * 8;
                float v0 = acc[mt][nt][half * 2 + 0] * alpha;
                float v1 = acc[mt][nt][half * 2 + 1] * alpha;
                if (bias) {
                    if (gn0 < N)     v0 += bias[gn0];
                    if (gn0 + 1 < N) v1 += bias[gn0 + 1];
                }
                if (do_gelu) { v0 = gelu_f(v0); v1 = gelu_f(v1); }
                long idx = (long)gm * ldc + gn0;
                if (Cin) {
                    if (gn0 < N)     v0 += Cin[idx];
                    if (gn0 + 1 < N) v1 += Cin[idx + 1];
                }
                if (gn0 + 1 < N) {
                    C[idx]     = v0;
                    C[idx + 1] = v1;
                } else if (gn0 < N) {
                    C[idx] = v0;
                }
            }
        }
    }
}

// ---------------- launch ----------------
extern "C" void kernel_launch(void* const* d_in, const int* in_sizes, int n_in,
                              void* d_out, int out_size) {
    const int*   ids    = (const int*)  d_in[0];
    const float* wte    = (const float*)d_in[1];
    const float* wpe    = (const float*)d_in[2];
    const float* ln1_g  = (const float*)d_in[3];
    const float* ln1_b  = (const float*)d_in[4];
    const float* W_attn = (const float*)d_in[5];
    const float* b_attn = (const float*)d_in[6];
    const float* W_ap   = (const float*)d_in[7];
    const float* b_ap   = (const float*)d_in[8];
    const float* ln2_g  = (const float*)d_in[9];
    const float* ln2_b  = (const float*)d_in[10];
    const float* W_fc   = (const float*)d_in[11];
    const float* b_fc   = (const float*)d_in[12];
    const float* W_proj = (const float*)d_in[13];
    const float* b_proj = (const float*)d_in[14];
    const float* lnf_g  = (const float*)d_in[15];
    const float* lnf_b  = (const float*)d_in[16];
    const float* W_lm   = (const float*)d_in[17];
    float* out = (float*)d_out;

    float *h, *x, *qkv, *q, *k, *v, *sc, *o, *fc;
    cudaGetSymbolAddress((void**)&h,   g_h);
    cudaGetSymbolAddress((void**)&x,   g_x);
    cudaGetSymbolAddress((void**)&qkv, g_qkv);
    cudaGetSymbolAddress((void**)&q,   g_q);
    cudaGetSymbolAddress((void**)&k,   g_k);
    cudaGetSymbolAddress((void**)&v,   g_v);
    cudaGetSymbolAddress((void**)&sc,  g_sc);
    cudaGetSymbolAddress((void**)&o,   g_o);
    cudaGetSymbolAddress((void**)&fc,  g_fc);

    // 1. embeddings
    embed_k<<<TT, 256>>>(ids, wte, wpe, h);
    // 2. ln1
    ln_k<<<TT, 256>>>(h, ln1_g, ln1_b, x);
    // 3. qkv = x @ W_attn + b_attn    [4096, 3072]
    {
        dim3 grd((3 * DD) / 128, TT / 128, 1);
        gemm_tc<128, 128, 16, 64, 64, false, true, false><<<grd, 128>>>(
            x, W_attn, b_attn, nullptr, qkv,
            TT, 3 * DD, DD, DD, 3 * DD, 3 * DD, 0, 0, 0, 1.0f, 0, 0);
    }
    // 4. split heads
    split_qkv_k<<<TT, 256>>>(qkv, q, k, v);
    // 5. scores = (Q @ K^T) / 8, batched over B*H, causal-skipped
    {
        dim3 grd(SS / 128, SS / 128, BB * HH);
        gemm_tc<128, 128, 16, 64, 64, true, true, false><<<grd, 128>>>(
            q, k, nullptr, nullptr, sc,
            SS, SS, HDD, HDD, HDD, SS,
            (long)SS * HDD, (long)SS * HDD, (long)SS * SS, 0.125f, 0, 1);
    }
    // 6. causal softmax in place
    softmax_k<<<BB * HH * SS, 256>>>(sc);
    // 7. O = P @ V, batched, K limited to causal boundary
    {
        dim3 grd(1, SS / 128, BB * HH);
        gemm_tc<128, 64, 16, 64, 32, false, true, false><<<grd, 128>>>(
            sc, v, nullptr, nullptr, o,
            SS, HDD, SS, SS, HDD, HDD,
            (long)SS * SS, (long)SS * HDD, (long)SS * HDD, 1.0f, 0, 2);
    }
    // 8. merge heads into x (reused as ao)
    merge_o_k<<<TT, 256>>>(o, x);
    // 9. h = h + ao @ W_ap + b_ap
    {
        dim3 grd(DD / 128, TT / 128, 1);
        gemm_tc<128, 128, 16, 64, 64, false, true, false><<<grd, 128>>>(
            x, W_ap, b_ap, h, h,
            TT, DD, DD, DD, DD, DD, 0, 0, 0, 1.0f, 0, 0);
    }
    // 10. ln2
    ln_k<<<TT, 256>>>(h, ln2_g, ln2_b, x);
    // 11. fc = gelu(x @ W_fc + b_fc)  [4096, 4096]
    {
        dim3 grd((4 * DD) / 128, TT / 128, 1);
        gemm_tc<128, 128, 16, 64, 64, false, true, false><<<grd, 128>>>(
            x, W_fc, b_fc, nullptr, fc,
            TT, 4 * DD, DD, DD, 4 * DD, 4 * DD, 0, 0, 0, 1.0f, 1, 0);
    }
    // 12. h = h + fc @ W_proj + b_proj
    {
        dim3 grd(DD / 128, TT / 128, 1);
        gemm_tc<128, 128, 16, 64, 64, false, true, false><<<grd, 128>>>(
            fc, W_proj, b_proj, h, h,
            TT, DD, 4 * DD, 4 * DD, DD, DD, 0, 0, 0, 1.0f, 0, 0);
    }
    // 13. lnf
    ln_k<<<TT, 256>>>(h, lnf_g, lnf_b, x);
    // 14. logits = x @ W_lm  [4096, 50257]; SWAPXY so one W_lm strip is shared
    //     by all 32 concurrent M-blocks (L2 reuse), unaligned B path.
    {
        dim3 grd(TT / 128, (VV + 127) / 128, 1);
        gemm_tc<128, 128, 16, 64, 64, false, false, true><<<grd, 128>>>(
            x, W_lm, nullptr, nullptr, out,
            TT, VV, DD, DD, VV, VV, 0, 0, 0, 1.0f, 0, 0);
    }
}